// round 15
// baseline (speedup 1.0000x reference)
#include <cuda_runtime.h>
#include <cuda_bf16.h>
#include <cuda_fp16.h>
#include <math.h>

#define NN   50000
#define EE   400000
#define EP   450000
#define IN_F 128
#define HIDF 16
#define H    11
#define HC   176
#define G    64

#define KP     176
#define KPRE   128
#define NP_CONV 576
#define NP_C5   384
#define NP_PRE  192

#define SZP_PRE   (NP_PRE * KPRE)
#define SZP_CONV  (NP_CONV * KP)
#define SZP_C5    (NP_C5 * KP)
#define OFFP_PRE  0
#define OFFP_CONV (OFFP_PRE + SZP_PRE)
#define OFFP_C5   (OFFP_CONV + 4 * SZP_CONV)
#define WP_TOTAL  (OFFP_C5 + SZP_C5)
#define BIAS_TOTAL (6 * NP_CONV)
#define PACK_TOTAL (WP_TOTAL + BIAS_TOTAL)

#define NODES_PER_BLK 23
#define ATT_THREADS   253          // 23 * 11

// ---------------- scratch ----------------
__device__ __half   g_xlr[(size_t)NN * 352];
__device__ float    g_res[(size_t)NN * HC];
__device__ float    g_buf[(size_t)NN * HC];
__device__ float    g_res16[(size_t)NN * HIDF];
__device__ __nv_bfloat16 g_ah[(size_t)NN * KP];
__device__ __nv_bfloat16 g_al[(size_t)NN * KP];
__device__ __nv_bfloat16 g_xh[(size_t)NN * KPRE];
__device__ __nv_bfloat16 g_xlo[(size_t)NN * KPRE];
__device__ __nv_bfloat16 g_pwh[WP_TOTAL];
__device__ __nv_bfloat16 g_pwl[WP_TOTAL];
__device__ float    g_pbias[BIAS_TOTAL];
__device__ float    g_sum[G * HC];
__device__ float    g_sq[G * HC];
__device__ float    g_mean[G * HC];
__device__ float    g_rstd[G * HC];
__device__ int      g_gncnt[G];
__device__ int      g_start[G + 1];
__device__ float    g_out16[(size_t)NN * HIDF];
__device__ int      g_deg[NN];
__device__ int      g_rowptr[NN + 1];
__device__ int      g_cursor[NN];
__device__ int      g_csr[EP];
__device__ int      g_bsum[256];
__device__ int      g_boff[256];

// ---------------- segment boundaries ----------------
__global__ void seg_mark(const int* __restrict__ batch, int* __restrict__ start) {
    int i = blockIdx.x * blockDim.x + threadIdx.x;
    if (i >= NN) return;
    if (i == 0 || batch[i] != batch[i - 1]) start[batch[i]] = i;
}
__global__ void seg_fix(int* start) {
    if (threadIdx.x == 0) {
        start[G] = NN;
        for (int g = G - 1; g >= 0; g--)
            if (start[g] < 0) start[g] = start[g + 1];
    }
}

// ---------------- CSR build ----------------
__global__ void deg_count(const int* __restrict__ ei) {
    int e = blockIdx.x * blockDim.x + threadIdx.x;
    if (e >= EP) return;
    int d = (e < EE) ? ei[EE + e] : (e - EE);
    atomicAdd(&g_deg[d], 1);
}
#define SCAN_B 256
__global__ void scan1(const int* __restrict__ in, int* __restrict__ out,
                      int* __restrict__ bsum, int n) {
    __shared__ int sh[SCAN_B];
    int i = blockIdx.x * SCAN_B + threadIdx.x;
    int v = (i < n) ? in[i] : 0;
    sh[threadIdx.x] = v;
    __syncthreads();
    for (int off = 1; off < SCAN_B; off <<= 1) {
        int t = (threadIdx.x >= off) ? sh[threadIdx.x - off] : 0;
        __syncthreads();
        sh[threadIdx.x] += t;
        __syncthreads();
    }
    if (i < n) out[i] = sh[threadIdx.x] - v;
    if (threadIdx.x == SCAN_B - 1 && bsum) bsum[blockIdx.x] = sh[threadIdx.x];
}
__global__ void scan_add(int* __restrict__ out, const int* __restrict__ boff, int n) {
    int i = blockIdx.x * SCAN_B + threadIdx.x;
    if (i < n) {
        int v = out[i] + boff[blockIdx.x];
        out[i] = v;
        g_cursor[i] = v;
    }
    if (i == 0) out[NN] = EP;
}
__global__ void csr_scatter(const int* __restrict__ ei) {
    int e = blockIdx.x * blockDim.x + threadIdx.x;
    if (e >= EP) return;
    int s, d;
    if (e < EE) { s = ei[e]; d = ei[EE + e]; }
    else        { s = e - EE; d = s; }
    int pos = atomicAdd(&g_cursor[d], 1);
    g_csr[pos] = s;
}

// ---------------- all weight packing ----------------
__global__ void pack_all(const float* __restrict__ W_pre,
                         const float* __restrict__ conv_Wl, const float* __restrict__ conv_Wr,
                         const float* __restrict__ conv_Wres,
                         const float* __restrict__ c5_Wl, const float* __restrict__ c5_Wr,
                         const float* __restrict__ c5_Wres,
                         const float* __restrict__ b_pre, const float* __restrict__ conv_b,
                         const float* __restrict__ c5_b) {
    int idx = blockIdx.x * blockDim.x + threadIdx.x;
    if (idx >= PACK_TOTAL) return;
    if (idx >= WP_TOTAL) {
        int t = idx - WP_TOTAL;
        int slot = t / NP_CONV, n = t - slot * NP_CONV;
        float v = 0.f;
        if (slot == 0)      { if (n < 176) v = b_pre[n]; }
        else if (slot <= 4) { if (n >= 352 && n < 528) v = conv_b[(slot - 1) * HC + (n - 352)]; }
        else                { if (n >= 352 && n < 368) v = c5_b[n - 352]; }
        g_pbias[t] = v;
        return;
    }
    float v = 0.f;
    if (idx < OFFP_CONV) {
        int n = idx / KPRE, k = idx - n * KPRE;
        if (n < HC) v = W_pre[(size_t)k * HC + n];
    } else if (idx < OFFP_C5) {
        int t = idx - OFFP_CONV;
        int L = t / SZP_CONV, r = t - L * SZP_CONV;
        int n = r / KP, k = r - n * KP;
        const float* Wl = conv_Wl + (size_t)L * HC * HC;
        const float* Wr = conv_Wr + (size_t)L * HC * HC;
        const float* Ws = conv_Wres + (size_t)L * HC * HC;
        if (n < 176)      v = Wl[(size_t)k * HC + n];
        else if (n < 352) v = Wr[(size_t)k * HC + (n - 176)];
        else if (n < 528) v = Ws[(size_t)k * HC + (n - 352)];
    } else {
        int r = idx - OFFP_C5;
        int n = r / KP, k = r - n * KP;
        if (n < 176)      v = c5_Wl[(size_t)k * HC + n];
        else if (n < 352) v = c5_Wr[(size_t)k * HC + (n - 176)];
        else if (n < 368) v = c5_Wres[(size_t)k * HIDF + (n - 352)];
    }
    __nv_bfloat16 h = __float2bfloat16(v);
    g_pwh[idx] = h;
    g_pwl[idx] = __float2bfloat16(v - __bfloat162float(h));
}

__device__ __forceinline__ unsigned pack2bf(float a, float b) {
    __nv_bfloat162 t = __floats2bfloat162_rn(a, b);
    return *reinterpret_cast<unsigned*>(&t);
}
__global__ void asplit_pre(const float* __restrict__ x) {
    int idx = blockIdx.x * blockDim.x + threadIdx.x;
    if (idx >= NN * KPRE / 4) return;
    float4 v = reinterpret_cast<const float4*>(x)[idx];
    float h0 = __bfloat162float(__float2bfloat16(v.x));
    float h1 = __bfloat162float(__float2bfloat16(v.y));
    float h2 = __bfloat162float(__float2bfloat16(v.z));
    float h3 = __bfloat162float(__float2bfloat16(v.w));
    reinterpret_cast<uint2*>(g_xh)[idx] = make_uint2(pack2bf(v.x, v.y), pack2bf(v.z, v.w));
    reinterpret_cast<uint2*>(g_xlo)[idx] =
        make_uint2(pack2bf(v.x - h0, v.y - h1), pack2bf(v.z - h2, v.w - h3));
}

// ---------------- BF16x3 tensor-core GEMM ----------------
#define ASTR 40

__device__ __forceinline__ void mma16816(float* c, const unsigned* a, const unsigned* b) {
    asm volatile(
        "mma.sync.aligned.m16n8k16.row.col.f32.bf16.bf16.f32 "
        "{%0,%1,%2,%3}, {%4,%5,%6,%7}, {%8,%9}, {%0,%1,%2,%3};\n"
        : "+f"(c[0]), "+f"(c[1]), "+f"(c[2]), "+f"(c[3])
        : "r"(a[0]), "r"(a[1]), "r"(a[2]), "r"(a[3]), "r"(b[0]), "r"(b[1]));
}
__device__ __forceinline__ void ldsm4(unsigned& r0, unsigned& r1, unsigned& r2, unsigned& r3,
                                      unsigned addr) {
    asm volatile("ldmatrix.sync.aligned.m8n8.x4.shared.b16 {%0,%1,%2,%3}, [%4];"
                 : "=r"(r0), "=r"(r1), "=r"(r2), "=r"(r3) : "r"(addr));
}
__device__ __forceinline__ void cpa16(unsigned dst, const void* src, bool pred) {
    int sz = pred ? 16 : 0;
    asm volatile("cp.async.cg.shared.global [%0], [%1], 16, %2;\n"
                 :: "r"(dst), "l"(src), "r"(sz));
}

__global__ __launch_bounds__(256, 3) void gemm3x(
    const __nv_bfloat16* __restrict__ Ah, const __nv_bfloat16* __restrict__ Al,
    const __nv_bfloat16* __restrict__ Wh, const __nv_bfloat16* __restrict__ Wl,
    const float* __restrict__ biasP,
    __half* __restrict__ out1, int s1, int c1,
    float* __restrict__ out2, int s2, int c2,
    int M, int KPv) {
    extern __shared__ __nv_bfloat16 sm[];
    __nv_bfloat16* sAh = sm;
    __nv_bfloat16* sAl = sAh + 2 * 128 * ASTR;
    __nv_bfloat16* sBh = sAl + 2 * 128 * ASTR;
    __nv_bfloat16* sBl = sBh + 2 * 64 * ASTR;

    int tid = threadIdx.x;
    int wid = tid >> 5, lane = tid & 31;
    int m0 = blockIdx.y * 128, n0 = blockIdx.x * 64;
    int wm = (wid >> 1) * 32, wn = (wid & 1) * 32;

    unsigned aB  = (unsigned)__cvta_generic_to_shared(sAh);
    unsigned alB = (unsigned)__cvta_generic_to_shared(sAl);
    unsigned bB  = (unsigned)__cvta_generic_to_shared(sBh);
    unsigned blB = (unsigned)__cvta_generic_to_shared(sBl);

    float c[2][4][4];
    #pragma unroll
    for (int i = 0; i < 2; i++)
        #pragma unroll
        for (int j = 0; j < 4; j++)
            #pragma unroll
            for (int k = 0; k < 4; k++) c[i][j][k] = 0.f;

    int KT = (KPv + 31) >> 5;

    auto loadTile = [&](int kt, int buf) {
        int k0 = kt * 32;
        #pragma unroll
        for (int i = 0; i < 4; i++) {
            int t = tid + i * 256;
            int half = t >> 9;
            int r = (t & 511) >> 2;
            int cc = t & 3;
            int kk = k0 + cc * 8;
            const __nv_bfloat16* src = (half ? Al : Ah) + (size_t)(m0 + r) * KPv + kk;
            unsigned dst = (half ? alB : aB) + (buf * 128 * ASTR + r * ASTR + cc * 8) * 2;
            cpa16(dst, src, (m0 + r) < M && kk < KPv);
        }
        #pragma unroll
        for (int i = 0; i < 2; i++) {
            int t = tid + i * 256;
            int half = t >> 8;
            int r = (t & 255) >> 2;
            int cc = t & 3;
            int kk = k0 + cc * 8;
            const __nv_bfloat16* src = (half ? Wl : Wh) + (size_t)(n0 + r) * KPv + kk;
            unsigned dst = (half ? blB : bB) + (buf * 64 * ASTR + r * ASTR + cc * 8) * 2;
            cpa16(dst, src, kk < KPv);
        }
        asm volatile("cp.async.commit_group;\n");
    };

    loadTile(0, 0);
    int arow = (lane & 7) + ((lane >> 3) & 1) * 8;
    int acol = (lane >> 4) * 8;
    int bi = lane >> 3;
    int nrow = ((bi >> 1) & 1) * 8 + (lane & 7);
    int kcol = (bi & 1) * 8;

    for (int kt = 0; kt < KT; kt++) {
        int buf = kt & 1;
        if (kt + 1 < KT) {
            loadTile(kt + 1, buf ^ 1);
            asm volatile("cp.async.wait_group 1;\n");
        } else {
            asm volatile("cp.async.wait_group 0;\n");
        }
        __syncthreads();

        int kbase = kt * 32;
        #pragma unroll
        for (int ks = 0; ks < 32; ks += 16) {
            if (kbase + ks >= KPv) break;
            unsigned ah[2][4], alr[2][4], bh[2][4], blr[2][4];
            #pragma unroll
            for (int mf = 0; mf < 2; mf++) {
                unsigned off = (buf * 128 * ASTR + (wm + mf * 16 + arow) * ASTR + ks + acol) * 2;
                ldsm4(ah[mf][0], ah[mf][1], ah[mf][2], ah[mf][3], aB + off);
                ldsm4(alr[mf][0], alr[mf][1], alr[mf][2], alr[mf][3], alB + off);
            }
            #pragma unroll
            for (int nf16 = 0; nf16 < 2; nf16++) {
                unsigned off = (buf * 64 * ASTR + (wn + nf16 * 16 + nrow) * ASTR + ks + kcol) * 2;
                ldsm4(bh[nf16][0], bh[nf16][1], bh[nf16][2], bh[nf16][3], bB + off);
                ldsm4(blr[nf16][0], blr[nf16][1], blr[nf16][2], blr[nf16][3], blB + off);
            }
            #pragma unroll
            for (int mf = 0; mf < 2; mf++)
                #pragma unroll
                for (int nf = 0; nf < 4; nf++)
                    mma16816(c[mf][nf], ah[mf], &bh[nf >> 1][(nf & 1) * 2]);
            #pragma unroll
            for (int mf = 0; mf < 2; mf++)
                #pragma unroll
                for (int nf = 0; nf < 4; nf++)
                    mma16816(c[mf][nf], ah[mf], &blr[nf >> 1][(nf & 1) * 2]);
            #pragma unroll
            for (int mf = 0; mf < 2; mf++)
                #pragma unroll
                for (int nf = 0; nf < 4; nf++)
                    mma16816(c[mf][nf], alr[mf], &bh[nf >> 1][(nf & 1) * 2]);
        }
        __syncthreads();
    }

    int r = lane >> 2, cq = (lane & 3) * 2;
    #pragma unroll
    for (int mf = 0; mf < 2; mf++)
        #pragma unroll
        for (int nf = 0; nf < 4; nf++) {
            int row = m0 + wm + mf * 16 + r;
            int col = n0 + wn + nf * 8 + cq;
            float2 bv = *reinterpret_cast<const float2*>(biasP + col);
            if (col < c1) {
                if (row < M) {
                    __half2 o = __floats2half2_rn(c[mf][nf][0] + bv.x, c[mf][nf][1] + bv.y);
                    *reinterpret_cast<__half2*>(out1 + (size_t)row * s1 + col) = o;
                }
                if (row + 8 < M) {
                    __half2 o = __floats2half2_rn(c[mf][nf][2] + bv.x, c[mf][nf][3] + bv.y);
                    *reinterpret_cast<__half2*>(out1 + (size_t)(row + 8) * s1 + col) = o;
                }
            } else if (col < c2) {
                float* p = out2 + (size_t)row * s2 + (col - c1);
                if (row < M) {
                    float2 o = make_float2(c[mf][nf][0] + bv.x, c[mf][nf][1] + bv.y);
                    *reinterpret_cast<float2*>(p) = o;
                }
                if (row + 8 < M) {
                    float2 o = make_float2(c[mf][nf][2] + bv.x, c[mf][nf][3] + bv.y);
                    *reinterpret_cast<float2*>(p + 8 * (size_t)s2) = o;
                }
            }
        }
}
#define GEMM_SMEM ((2 * 2 * 128 * ASTR + 2 * 2 * 64 * ASTR) * 2)

// ---------------- GraphNorm ----------------
#define PARTS 32
// full stats kernel — used only for layer 0 (pre-layer output)
__global__ void gn_fused(const float* __restrict__ x, const float* __restrict__ gn_ms,
                         int layer) {
    int g = blockIdx.x;
    int part = blockIdx.y;
    int f = threadIdx.x;
    __shared__ int lastFlag;
    if (f < HC) {
        int s0 = g_start[g], s1 = g_start[g + 1];
        float sum = 0.f, sq = 0.f;
        for (int n = s0 + part; n < s1; n += PARTS) {
            float v = x[(size_t)n * HC + f];
            sum += v;
            sq += v * v;
        }
        atomicAdd(&g_sum[g * HC + f], sum);
        atomicAdd(&g_sq[g * HC + f], sq);
    }
    __threadfence();
    __syncthreads();
    if (threadIdx.x == 0) {
        int t = atomicAdd(&g_gncnt[g], 1);
        lastFlag = (t == PARTS - 1);
    }
    __syncthreads();
    if (lastFlag && f < HC) {
        int idx = g * HC + f;
        float cnt = fmaxf((float)(g_start[g + 1] - g_start[g]), 1.f);
        float m = g_sum[idx] / cnt;
        float ms = gn_ms[layer * HC + f];
        float var = g_sq[idx] / cnt + m * m * (ms * ms - 2.f * ms);
        g_mean[idx] = m;
        g_rstd[idx] = 1.f / sqrtf(var + 1e-5f);
        g_sum[idx] = 0.f;
        g_sq[idx] = 0.f;
        if (f == 0) g_gncnt[g] = 0;
    }
}
// finalize only — stats already accumulated by attn_fused epilogue (layers 1..4)
__global__ void gn_finalize(const float* __restrict__ gn_ms, int layer) {
    int idx = blockIdx.x * blockDim.x + threadIdx.x;
    if (idx >= G * HC) return;
    int g = idx / HC, f = idx - g * HC;
    float cnt = fmaxf((float)(g_start[g + 1] - g_start[g]), 1.f);
    float m = g_sum[idx] / cnt;
    float ms = gn_ms[layer * HC + f];
    float var = g_sq[idx] / cnt + m * m * (ms * ms - 2.f * ms);
    g_mean[idx] = m;
    g_rstd[idx] = 1.f / sqrtf(var + 1e-5f);
    g_sum[idx] = 0.f;
    g_sq[idx] = 0.f;
}
__global__ void gn_norm_split(const float* __restrict__ x,
                              const float* __restrict__ gn_w, const float* __restrict__ gn_b,
                              const float* __restrict__ gn_ms, int layer,
                              const int* __restrict__ batch) {
    int idx = blockIdx.x * blockDim.x + threadIdx.x;
    if (idx >= NN * HC / 4) return;
    int n = idx / (HC / 4), f4 = idx - n * (HC / 4);
    int f = f4 * 4;
    int g = batch[n];
    float4 xv = reinterpret_cast<const float4*>(x)[idx];
    float4 wv = *reinterpret_cast<const float4*>(gn_w + layer * HC + f);
    float4 bv = *reinterpret_cast<const float4*>(gn_b + layer * HC + f);
    float4 msv = *reinterpret_cast<const float4*>(gn_ms + layer * HC + f);
    float4 mv = *reinterpret_cast<const float4*>(g_mean + g * HC + f);
    float4 rv = *reinterpret_cast<const float4*>(g_rstd + g * HC + f);
    float o0 = fmaxf((xv.x - msv.x * mv.x) * rv.x * wv.x + bv.x, 0.f);
    float o1 = fmaxf((xv.y - msv.y * mv.y) * rv.y * wv.y + bv.y, 0.f);
    float o2 = fmaxf((xv.z - msv.z * mv.z) * rv.z * wv.z + bv.z, 0.f);
    float o3 = fmaxf((xv.w - msv.w * mv.w) * rv.w * wv.w + bv.w, 0.f);
    float h0 = __bfloat162float(__float2bfloat16(o0));
    float h1 = __bfloat162float(__float2bfloat16(o1));
    float h2 = __bfloat162float(__float2bfloat16(o2));
    float h3 = __bfloat162float(__float2bfloat16(o3));
    reinterpret_cast<uint2*>(g_ah)[idx] = make_uint2(pack2bf(o0, o1), pack2bf(o2, o3));
    reinterpret_cast<uint2*>(g_al)[idx] =
        make_uint2(pack2bf(o0 - h0, o1 - h1), pack2bf(o2 - h2, o3 - h3));
}

// ---------------- fused GATv2 attention + GN stats epilogue ----------------
__device__ __forceinline__ void h8_to_f(const uint4& u, float* dst) {
    const __half2* hp = reinterpret_cast<const __half2*>(&u);
    #pragma unroll
    for (int j = 0; j < 4; j++) {
        float2 f = __half22float2(hp[j]);
        dst[2 * j] = f.x;
        dst[2 * j + 1] = f.y;
    }
}
__global__ __launch_bounds__(ATT_THREADS) void attn_fused(
    const float* __restrict__ att,
    float* __restrict__ outbuf, int ostride, int addResid, int doStats,
    const int* __restrict__ batch) {
    __shared__ float s_out[NODES_PER_BLK][HC];
    __shared__ int   s_b[NODES_PER_BLK];

    int t = threadIdx.x;
    int ni = t / H, h = t - ni * H;
    int n = blockIdx.x * NODES_PER_BLK + ni;
    bool valid = (n < NN);

    float vals[16];
    if (valid) {
        const uint4* xrp = reinterpret_cast<const uint4*>(
            g_xlr + (size_t)n * 352 + 176 + h * HIDF);
        const float* atp = att + h * HIDF;
        float xr[16], at[16];
        {
            uint4 u0 = xrp[0], u1 = xrp[1];
            h8_to_f(u0, xr);
            h8_to_f(u1, xr + 8);
        }
        #pragma unroll
        for (int i = 0; i < 4; i++) {
            float4 a = reinterpret_cast<const float4*>(atp)[i];
            at[i*4+0] = a.x; at[i*4+1] = a.y; at[i*4+2] = a.z; at[i*4+3] = a.w;
        }

        float den = 0.f;
        float acc[16];
        #pragma unroll
        for (int j = 0; j < 16; j++) acc[j] = 0.f;

        int e = g_rowptr[n], e1 = g_rowptr[n + 1];
        for (; e + 2 <= e1; e += 2) {
            int s0 = g_csr[e];
            int s1 = g_csr[e + 1];
            const uint4* p0 = reinterpret_cast<const uint4*>(g_xlr + (size_t)s0 * 352 + h * HIDF);
            const uint4* p1 = reinterpret_cast<const uint4*>(g_xlr + (size_t)s1 * 352 + h * HIDF);
            uint4 u00 = p0[0], u01 = p0[1], u10 = p1[0], u11 = p1[1];
            float xl0[16], xl1[16];
            h8_to_f(u00, xl0); h8_to_f(u01, xl0 + 8);
            h8_to_f(u10, xl1); h8_to_f(u11, xl1 + 8);
            float a0 = 0.f, a1 = 0.f;
            #pragma unroll
            for (int j = 0; j < 16; j++) {
                float t0 = xl0[j] + xr[j];
                t0 = t0 > 0.f ? t0 : 0.2f * t0;
                a0 = fmaf(t0, at[j], a0);
                float t1 = xl1[j] + xr[j];
                t1 = t1 > 0.f ? t1 : 0.2f * t1;
                a1 = fmaf(t1, at[j], a1);
            }
            float ex0 = __expf(a0);
            float ex1 = __expf(a1);
            den += ex0 + ex1;
            #pragma unroll
            for (int j = 0; j < 16; j++)
                acc[j] = fmaf(ex1, xl1[j], fmaf(ex0, xl0[j], acc[j]));
        }
        if (e < e1) {
            int s = g_csr[e];
            const uint4* pl = reinterpret_cast<const uint4*>(g_xlr + (size_t)s * 352 + h * HIDF);
            uint4 u0 = pl[0], u1 = pl[1];
            float xl[16];
            h8_to_f(u0, xl);
            h8_to_f(u1, xl + 8);
            float alpha = 0.f;
            #pragma unroll
            for (int j = 0; j < 16; j++) {
                float v = xl[j] + xr[j];
                v = v > 0.f ? v : 0.2f * v;
                alpha = fmaf(v, at[j], alpha);
            }
            float ex = __expf(alpha);
            den += ex;
            #pragma unroll
            for (int j = 0; j < 16; j++) acc[j] = fmaf(ex, xl[j], acc[j]);
        }
        float inv = 1.f / (den + 1e-16f);
        float* op = outbuf + (size_t)n * ostride + h * HIDF;
        #pragma unroll
        for (int j = 0; j < 16; j++) {
            float base = addResid ? op[j] : 0.f;
            vals[j] = base + acc[j] * inv;
            op[j] = vals[j];
        }
        if (doStats) {
            #pragma unroll
            for (int j = 0; j < 16; j++) s_out[ni][h * HIDF + j] = vals[j];
            if (h == 0) s_b[ni] = batch[n];
        }
    }

    if (!doStats) return;
    __syncthreads();
    if (t < HC) {
        int f = t;
        float sum = 0.f, sq = 0.f;
        int curg = -1;
        #pragma unroll 1
        for (int i = 0; i < NODES_PER_BLK; i++) {
            int nn2 = blockIdx.x * NODES_PER_BLK + i;
            if (nn2 >= NN) break;
            int g = s_b[i];
            if (g != curg) {
                if (curg >= 0) {
                    atomicAdd(&g_sum[curg * HC + f], sum);
                    atomicAdd(&g_sq[curg * HC + f], sq);
                }
                curg = g;
                sum = 0.f;
                sq = 0.f;
            }
            float v = s_out[i][f];
            sum += v;
            sq += v * v;
        }
        if (curg >= 0) {
            atomicAdd(&g_sum[curg * HC + f], sum);
            atomicAdd(&g_sq[curg * HC + f], sq);
        }
    }
}

// ---------------- conv5 head mean + relu ----------------
__global__ void head_mean_relu() {
    int idx = blockIdx.x * blockDim.x + threadIdx.x;
    if (idx >= NN * HIDF) return;
    int n = idx / HIDF, c = idx - n * HIDF;
    float res = g_res16[idx];
    float s = 0.f;
    #pragma unroll
    for (int h = 0; h < H; h++) s += g_buf[(size_t)n * HC + h * HIDF + c];
    g_out16[idx] = fmaxf(res + s * (1.f / (float)H), 0.f);
}

// ---------------- final fused MLP ----------------
__global__ void mlp(const float* __restrict__ Wo1, const float* __restrict__ bo1,
                    const float* __restrict__ Wo2, const float* __restrict__ bo2,
                    const float* __restrict__ Wc,  const float* __restrict__ bc,
                    float* __restrict__ out) {
    __shared__ float w1[16 * 16], w2[16 * 32], w3[32 * 10], b1[16], b2[32], b3[10];
    int tid = threadIdx.x;
    if (tid < 256) w1[tid] = Wo1[tid];
    for (int t = tid; t < 512; t += blockDim.x) w2[t] = Wo2[t];
    for (int t = tid; t < 320; t += blockDim.x) w3[t] = Wc[t];
    if (tid < 16) b1[tid] = bo1[tid];
    if (tid < 32) b2[tid] = bo2[tid];
    if (tid < 10) b3[tid] = bc[tid];
    __syncthreads();
    int n = blockIdx.x * blockDim.x + tid;
    if (n >= NN) return;
    float a[16];
    #pragma unroll
    for (int i = 0; i < 16; i++) a[i] = g_out16[(size_t)n * 16 + i];
    float t1[16];
    #pragma unroll
    for (int j = 0; j < 16; j++) {
        float acc = b1[j];
        #pragma unroll
        for (int i = 0; i < 16; i++) acc += a[i] * w1[i * 16 + j];
        t1[j] = fmaxf(acc, 0.f);
    }
    float t2[32];
    #pragma unroll
    for (int j = 0; j < 32; j++) {
        float acc = b2[j];
        #pragma unroll
        for (int i = 0; i < 16; i++) acc += t1[i] * w2[i * 32 + j];
        t2[j] = fmaxf(acc, 0.f);
    }
    #pragma unroll
    for (int j = 0; j < 10; j++) {
        float acc = b3[j];
        #pragma unroll
        for (int k = 0; k < 32; k++) acc += t2[k] * w3[k * 10 + j];
        out[(size_t)n * 10 + j] = acc;
    }
}

// ---------------- host launch ----------------
extern "C" void kernel_launch(void* const* d_in, const int* in_sizes, int n_in,
                              void* d_out, int out_size) {
    const float* x        = (const float*)d_in[0];
    const int*   ei       = (const int*)d_in[1];
    const int*   batch    = (const int*)d_in[2];
    const float* W_pre    = (const float*)d_in[3];
    const float* b_pre    = (const float*)d_in[4];
    const float* gn_w     = (const float*)d_in[5];
    const float* gn_b     = (const float*)d_in[6];
    const float* gn_ms    = (const float*)d_in[7];
    const float* conv_Wl  = (const float*)d_in[8];
    const float* conv_Wr  = (const float*)d_in[9];
    const float* conv_att = (const float*)d_in[10];
    const float* conv_b   = (const float*)d_in[11];
    const float* conv_Wres= (const float*)d_in[12];
    const float* c5_Wl    = (const float*)d_in[13];
    const float* c5_Wr    = (const float*)d_in[14];
    const float* c5_att   = (const float*)d_in[15];
    const float* c5_b     = (const float*)d_in[16];
    const float* c5_Wres  = (const float*)d_in[17];
    const float* W_o1     = (const float*)d_in[18];
    const float* b_o1     = (const float*)d_in[19];
    const float* W_o2     = (const float*)d_in[20];
    const float* b_o2     = (const float*)d_in[21];
    const float* W_cls    = (const float*)d_in[22];
    const float* b_cls    = (const float*)d_in[23];
    float* out = (float*)d_out;

    float *p_res, *p_buf, *p_res16, *p_sum, *p_sq, *p_pbias;
    __half* p_xlr;
    __nv_bfloat16 *p_ah, *p_al, *p_xh, *p_xlo, *p_pwh, *p_pwl;
    int *p_start, *p_deg, *p_rowptr, *p_bsum, *p_boff, *p_gncnt;
    cudaGetSymbolAddress((void**)&p_xlr, g_xlr);
    cudaGetSymbolAddress((void**)&p_res, g_res);
    cudaGetSymbolAddress((void**)&p_buf, g_buf);
    cudaGetSymbolAddress((void**)&p_res16, g_res16);
    cudaGetSymbolAddress((void**)&p_sum, g_sum);
    cudaGetSymbolAddress((void**)&p_sq, g_sq);
    cudaGetSymbolAddress((void**)&p_pbias, g_pbias);
    cudaGetSymbolAddress((void**)&p_ah, g_ah);
    cudaGetSymbolAddress((void**)&p_al, g_al);
    cudaGetSymbolAddress((void**)&p_xh, g_xh);
    cudaGetSymbolAddress((void**)&p_xlo, g_xlo);
    cudaGetSymbolAddress((void**)&p_pwh, g_pwh);
    cudaGetSymbolAddress((void**)&p_pwl, g_pwl);
    cudaGetSymbolAddress((void**)&p_start, g_start);
    cudaGetSymbolAddress((void**)&p_deg, g_deg);
    cudaGetSymbolAddress((void**)&p_rowptr, g_rowptr);
    cudaGetSymbolAddress((void**)&p_bsum, g_bsum);
    cudaGetSymbolAddress((void**)&p_boff, g_boff);
    cudaGetSymbolAddress((void**)&p_gncnt, g_gncnt);

    static int initDone = 0;
    static cudaStream_t sSide;
    static cudaEvent_t evFork, evJoin;
    if (!initDone) {
        cudaFuncSetAttribute(gemm3x, cudaFuncAttributeMaxDynamicSharedMemorySize, GEMM_SMEM);
        cudaStreamCreateWithFlags(&sSide, cudaStreamNonBlocking);
        cudaEventCreateWithFlags(&evFork, cudaEventDisableTiming);
        cudaEventCreateWithFlags(&evJoin, cudaEventDisableTiming);
        initDone = 1;
    }

    auto gemm = [&](const __nv_bfloat16* Ah, const __nv_bfloat16* Al, int woff, int bslot,
                    __half* o1, int s1v, int c1v, float* o2, int s2v, int c2v,
                    int NPv, int KPv) {
        dim3 grid(NPv / 64, (NN + 127) / 128);
        gemm3x<<<grid, 256, GEMM_SMEM>>>(Ah, Al, p_pwh + woff, p_pwl + woff,
                                         p_pbias + bslot * NP_CONV,
                                         o1, s1v, c1v, o2, s2v, c2v, NN, KPv);
    };

    // fork side stream: CSR build
    cudaEventRecord(evFork, 0);
    cudaStreamWaitEvent(sSide, evFork, 0);
    {
        const int NBLK = (NN + SCAN_B - 1) / SCAN_B;
        cudaMemsetAsync(p_deg, 0, NN * sizeof(int), sSide);
        deg_count<<<(EP + 255) / 256, 256, 0, sSide>>>(ei);
        scan1<<<NBLK, SCAN_B, 0, sSide>>>(p_deg, p_rowptr, p_bsum, NN);
        scan1<<<1, SCAN_B, 0, sSide>>>(p_bsum, p_boff, nullptr, NBLK);
        scan_add<<<NBLK, SCAN_B, 0, sSide>>>(p_rowptr, p_boff, NN);
        csr_scatter<<<(EP + 255) / 256, 256, 0, sSide>>>(ei);
        cudaEventRecord(evJoin, sSide);
    }

    // main stream
    cudaMemsetAsync(p_start, 0xFF, (G + 1) * sizeof(int));
    cudaMemsetAsync(p_sum, 0, G * HC * sizeof(float));
    cudaMemsetAsync(p_sq, 0, G * HC * sizeof(float));
    cudaMemsetAsync(p_gncnt, 0, G * sizeof(int));

    pack_all<<<(PACK_TOTAL + 255) / 256, 256>>>(W_pre, conv_Wl, conv_Wr, conv_Wres,
                                                c5_Wl, c5_Wr, c5_Wres,
                                                b_pre, conv_b, c5_b);
    asplit_pre<<<(NN * KPRE / 4 + 255) / 256, 256>>>(x);
    seg_mark<<<(NN + 255) / 256, 256>>>(batch, p_start);
    gemm(p_xh, p_xlo, OFFP_PRE, 0, nullptr, 0, 0, p_res, HC, HC, NP_PRE, KPRE);
    seg_fix<<<1, 32>>>(p_start);
    // layer 0: full stats kernel (no attention before it)
    {
        dim3 sgrid(G, PARTS);
        gn_fused<<<sgrid, 192>>>(p_res, gn_ms, 0);
        gn_norm_split<<<(NN * HC / 4 + 255) / 256, 256>>>(p_res, gn_w, gn_b, gn_ms, 0, batch);
    }

    cudaStreamWaitEvent(0, evJoin, 0);

    const int attGrid = (NN + NODES_PER_BLK - 1) / NODES_PER_BLK;

    for (int L = 0; L < 4; L++) {
        gemm(p_ah, p_al, OFFP_CONV + L * SZP_CONV, 1 + L,
             p_xlr, 352, 352, p_res, HC, 528, NP_CONV, KP);
        attn_fused<<<attGrid, ATT_THREADS>>>(conv_att + L * H * HIDF, p_res, HC, 1, 1, batch);
        gn_finalize<<<(G * HC + 255) / 256, 256>>>(gn_ms, L + 1);
        gn_norm_split<<<(NN * HC / 4 + 255) / 256, 256>>>(p_res, gn_w, gn_b, gn_ms, L + 1, batch);
    }

    gemm(p_ah, p_al, OFFP_C5, 5,
         p_xlr, 352, 352, p_res16, HIDF, 368, NP_C5, KP);
    attn_fused<<<attGrid, ATT_THREADS>>>(c5_att, p_buf, HC, 0, 0, batch);
    head_mean_relu<<<(NN * HIDF + 255) / 256, 256>>>();

    mlp<<<(NN + 255) / 256, 256>>>(W_o1, b_o1, W_o2, b_o2, W_cls, b_cls, out);
}

// round 16
// speedup vs baseline: 1.1294x; 1.1294x over previous
#include <cuda_runtime.h>
#include <cuda_bf16.h>
#include <cuda_fp16.h>
#include <math.h>

#define NN   50000
#define EE   400000
#define EP   450000
#define IN_F 128
#define HIDF 16
#define H    11
#define HC   176
#define G    64

#define KP     176
#define KPRE   128
#define NP_CONV 576
#define NP_C5   384
#define NP_PRE  192

#define SZP_PRE   (NP_PRE * KPRE)
#define SZP_CONV  (NP_CONV * KP)
#define SZP_C5    (NP_C5 * KP)
#define OFFP_PRE  0
#define OFFP_CONV (OFFP_PRE + SZP_PRE)
#define OFFP_C5   (OFFP_CONV + 4 * SZP_CONV)
#define WP_TOTAL  (OFFP_C5 + SZP_C5)
#define BIAS_TOTAL (6 * NP_CONV)
#define PACK_TOTAL (WP_TOTAL + BIAS_TOTAL)

// ---------------- scratch ----------------
__device__ __half   g_xlr[(size_t)NN * 352];        // fp16 gather target
__device__ __half   g_res[(size_t)NN * HC];         // fp16 residual / gn input
__device__ __half   g_buf[(size_t)NN * HC];         // fp16 c5 attention agg
__device__ __half   g_res16[(size_t)NN * HIDF];
__device__ __nv_bfloat16 g_ah[(size_t)NN * KP];
__device__ __nv_bfloat16 g_al[(size_t)NN * KP];
__device__ __nv_bfloat16 g_xh[(size_t)NN * KPRE];
__device__ __nv_bfloat16 g_xlo[(size_t)NN * KPRE];
__device__ __nv_bfloat16 g_pwh[WP_TOTAL];
__device__ __nv_bfloat16 g_pwl[WP_TOTAL];
__device__ float    g_pbias[BIAS_TOTAL];
__device__ float    g_sum[G * HC];
__device__ float    g_sq[G * HC];
__device__ float    g_mean[G * HC];
__device__ float    g_rstd[G * HC];
__device__ int      g_gncnt[G];
__device__ int      g_start[G + 1];
__device__ float    g_out16[(size_t)NN * HIDF];
__device__ int      g_deg[NN];
__device__ int      g_rowptr[NN + 1];
__device__ int      g_cursor[NN];
__device__ int      g_csr[EP];
__device__ int      g_bsum[256];
__device__ int      g_boff[256];

// ---------------- segment boundaries ----------------
__global__ void seg_mark(const int* __restrict__ batch, int* __restrict__ start) {
    int i = blockIdx.x * blockDim.x + threadIdx.x;
    if (i >= NN) return;
    if (i == 0 || batch[i] != batch[i - 1]) start[batch[i]] = i;
}
__global__ void seg_fix(int* start) {
    if (threadIdx.x == 0) {
        start[G] = NN;
        for (int g = G - 1; g >= 0; g--)
            if (start[g] < 0) start[g] = start[g + 1];
    }
}

// ---------------- CSR build ----------------
__global__ void deg_count(const int* __restrict__ ei) {
    int e = blockIdx.x * blockDim.x + threadIdx.x;
    if (e >= EP) return;
    int d = (e < EE) ? ei[EE + e] : (e - EE);
    atomicAdd(&g_deg[d], 1);
}
#define SCAN_B 256
__global__ void scan1(const int* __restrict__ in, int* __restrict__ out,
                      int* __restrict__ bsum, int n) {
    __shared__ int sh[SCAN_B];
    int i = blockIdx.x * SCAN_B + threadIdx.x;
    int v = (i < n) ? in[i] : 0;
    sh[threadIdx.x] = v;
    __syncthreads();
    for (int off = 1; off < SCAN_B; off <<= 1) {
        int t = (threadIdx.x >= off) ? sh[threadIdx.x - off] : 0;
        __syncthreads();
        sh[threadIdx.x] += t;
        __syncthreads();
    }
    if (i < n) out[i] = sh[threadIdx.x] - v;
    if (threadIdx.x == SCAN_B - 1 && bsum) bsum[blockIdx.x] = sh[threadIdx.x];
}
__global__ void scan_add(int* __restrict__ out, const int* __restrict__ boff, int n) {
    int i = blockIdx.x * SCAN_B + threadIdx.x;
    if (i < n) {
        int v = out[i] + boff[blockIdx.x];
        out[i] = v;
        g_cursor[i] = v;
    }
    if (i == 0) out[NN] = EP;
}
__global__ void csr_scatter(const int* __restrict__ ei) {
    int e = blockIdx.x * blockDim.x + threadIdx.x;
    if (e >= EP) return;
    int s, d;
    if (e < EE) { s = ei[e]; d = ei[EE + e]; }
    else        { s = e - EE; d = s; }
    int pos = atomicAdd(&g_cursor[d], 1);
    g_csr[pos] = s;
}

// ---------------- all weight packing ----------------
__global__ void pack_all(const float* __restrict__ W_pre,
                         const float* __restrict__ conv_Wl, const float* __restrict__ conv_Wr,
                         const float* __restrict__ conv_Wres,
                         const float* __restrict__ c5_Wl, const float* __restrict__ c5_Wr,
                         const float* __restrict__ c5_Wres,
                         const float* __restrict__ b_pre, const float* __restrict__ conv_b,
                         const float* __restrict__ c5_b) {
    int idx = blockIdx.x * blockDim.x + threadIdx.x;
    if (idx >= PACK_TOTAL) return;
    if (idx >= WP_TOTAL) {
        int t = idx - WP_TOTAL;
        int slot = t / NP_CONV, n = t - slot * NP_CONV;
        float v = 0.f;
        if (slot == 0)      { if (n < 176) v = b_pre[n]; }
        else if (slot <= 4) { if (n >= 352 && n < 528) v = conv_b[(slot - 1) * HC + (n - 352)]; }
        else                { if (n >= 352 && n < 368) v = c5_b[n - 352]; }
        g_pbias[t] = v;
        return;
    }
    float v = 0.f;
    if (idx < OFFP_CONV) {
        int n = idx / KPRE, k = idx - n * KPRE;
        if (n < HC) v = W_pre[(size_t)k * HC + n];
    } else if (idx < OFFP_C5) {
        int t = idx - OFFP_CONV;
        int L = t / SZP_CONV, r = t - L * SZP_CONV;
        int n = r / KP, k = r - n * KP;
        const float* Wl = conv_Wl + (size_t)L * HC * HC;
        const float* Wr = conv_Wr + (size_t)L * HC * HC;
        const float* Ws = conv_Wres + (size_t)L * HC * HC;
        if (n < 176)      v = Wl[(size_t)k * HC + n];
        else if (n < 352) v = Wr[(size_t)k * HC + (n - 176)];
        else if (n < 528) v = Ws[(size_t)k * HC + (n - 352)];
    } else {
        int r = idx - OFFP_C5;
        int n = r / KP, k = r - n * KP;
        if (n < 176)      v = c5_Wl[(size_t)k * HC + n];
        else if (n < 352) v = c5_Wr[(size_t)k * HC + (n - 176)];
        else if (n < 368) v = c5_Wres[(size_t)k * HIDF + (n - 352)];
    }
    __nv_bfloat16 h = __float2bfloat16(v);
    g_pwh[idx] = h;
    g_pwl[idx] = __float2bfloat16(v - __bfloat162float(h));
}

__device__ __forceinline__ unsigned pack2bf(float a, float b) {
    __nv_bfloat162 t = __floats2bfloat162_rn(a, b);
    return *reinterpret_cast<unsigned*>(&t);
}
__global__ void asplit_pre(const float* __restrict__ x) {
    int idx = blockIdx.x * blockDim.x + threadIdx.x;
    if (idx >= NN * KPRE / 4) return;
    float4 v = reinterpret_cast<const float4*>(x)[idx];
    float h0 = __bfloat162float(__float2bfloat16(v.x));
    float h1 = __bfloat162float(__float2bfloat16(v.y));
    float h2 = __bfloat162float(__float2bfloat16(v.z));
    float h3 = __bfloat162float(__float2bfloat16(v.w));
    reinterpret_cast<uint2*>(g_xh)[idx] = make_uint2(pack2bf(v.x, v.y), pack2bf(v.z, v.w));
    reinterpret_cast<uint2*>(g_xlo)[idx] =
        make_uint2(pack2bf(v.x - h0, v.y - h1), pack2bf(v.z - h2, v.w - h3));
}

// ---------------- BF16x3 tensor-core GEMM ----------------
#define ASTR 40

__device__ __forceinline__ void mma16816(float* c, const unsigned* a, const unsigned* b) {
    asm volatile(
        "mma.sync.aligned.m16n8k16.row.col.f32.bf16.bf16.f32 "
        "{%0,%1,%2,%3}, {%4,%5,%6,%7}, {%8,%9}, {%0,%1,%2,%3};\n"
        : "+f"(c[0]), "+f"(c[1]), "+f"(c[2]), "+f"(c[3])
        : "r"(a[0]), "r"(a[1]), "r"(a[2]), "r"(a[3]), "r"(b[0]), "r"(b[1]));
}
__device__ __forceinline__ void ldsm4(unsigned& r0, unsigned& r1, unsigned& r2, unsigned& r3,
                                      unsigned addr) {
    asm volatile("ldmatrix.sync.aligned.m8n8.x4.shared.b16 {%0,%1,%2,%3}, [%4];"
                 : "=r"(r0), "=r"(r1), "=r"(r2), "=r"(r3) : "r"(addr));
}
__device__ __forceinline__ void cpa16(unsigned dst, const void* src, bool pred) {
    int sz = pred ? 16 : 0;
    asm volatile("cp.async.cg.shared.global [%0], [%1], 16, %2;\n"
                 :: "r"(dst), "l"(src), "r"(sz));
}

// out1: fp16 (cols [0,c1)); out2: fp16 (cols [c1,c2))
__global__ __launch_bounds__(256, 3) void gemm3x(
    const __nv_bfloat16* __restrict__ Ah, const __nv_bfloat16* __restrict__ Al,
    const __nv_bfloat16* __restrict__ Wh, const __nv_bfloat16* __restrict__ Wl,
    const float* __restrict__ biasP,
    __half* __restrict__ out1, int s1, int c1,
    __half* __restrict__ out2, int s2, int c2,
    int M, int KPv) {
    extern __shared__ __nv_bfloat16 sm[];
    __nv_bfloat16* sAh = sm;
    __nv_bfloat16* sAl = sAh + 2 * 128 * ASTR;
    __nv_bfloat16* sBh = sAl + 2 * 128 * ASTR;
    __nv_bfloat16* sBl = sBh + 2 * 64 * ASTR;

    int tid = threadIdx.x;
    int wid = tid >> 5, lane = tid & 31;
    int m0 = blockIdx.y * 128, n0 = blockIdx.x * 64;
    int wm = (wid >> 1) * 32, wn = (wid & 1) * 32;

    unsigned aB  = (unsigned)__cvta_generic_to_shared(sAh);
    unsigned alB = (unsigned)__cvta_generic_to_shared(sAl);
    unsigned bB  = (unsigned)__cvta_generic_to_shared(sBh);
    unsigned blB = (unsigned)__cvta_generic_to_shared(sBl);

    float c[2][4][4];
    #pragma unroll
    for (int i = 0; i < 2; i++)
        #pragma unroll
        for (int j = 0; j < 4; j++)
            #pragma unroll
            for (int k = 0; k < 4; k++) c[i][j][k] = 0.f;

    int KT = (KPv + 31) >> 5;

    auto loadTile = [&](int kt, int buf) {
        int k0 = kt * 32;
        #pragma unroll
        for (int i = 0; i < 4; i++) {
            int t = tid + i * 256;
            int half = t >> 9;
            int r = (t & 511) >> 2;
            int cc = t & 3;
            int kk = k0 + cc * 8;
            const __nv_bfloat16* src = (half ? Al : Ah) + (size_t)(m0 + r) * KPv + kk;
            unsigned dst = (half ? alB : aB) + (buf * 128 * ASTR + r * ASTR + cc * 8) * 2;
            cpa16(dst, src, (m0 + r) < M && kk < KPv);
        }
        #pragma unroll
        for (int i = 0; i < 2; i++) {
            int t = tid + i * 256;
            int half = t >> 8;
            int r = (t & 255) >> 2;
            int cc = t & 3;
            int kk = k0 + cc * 8;
            const __nv_bfloat16* src = (half ? Wl : Wh) + (size_t)(n0 + r) * KPv + kk;
            unsigned dst = (half ? blB : bB) + (buf * 64 * ASTR + r * ASTR + cc * 8) * 2;
            cpa16(dst, src, kk < KPv);
        }
        asm volatile("cp.async.commit_group;\n");
    };

    loadTile(0, 0);
    int arow = (lane & 7) + ((lane >> 3) & 1) * 8;
    int acol = (lane >> 4) * 8;
    int bi = lane >> 3;
    int nrow = ((bi >> 1) & 1) * 8 + (lane & 7);
    int kcol = (bi & 1) * 8;

    for (int kt = 0; kt < KT; kt++) {
        int buf = kt & 1;
        if (kt + 1 < KT) {
            loadTile(kt + 1, buf ^ 1);
            asm volatile("cp.async.wait_group 1;\n");
        } else {
            asm volatile("cp.async.wait_group 0;\n");
        }
        __syncthreads();

        int kbase = kt * 32;
        #pragma unroll
        for (int ks = 0; ks < 32; ks += 16) {
            if (kbase + ks >= KPv) break;
            unsigned ah[2][4], alr[2][4], bh[2][4], blr[2][4];
            #pragma unroll
            for (int mf = 0; mf < 2; mf++) {
                unsigned off = (buf * 128 * ASTR + (wm + mf * 16 + arow) * ASTR + ks + acol) * 2;
                ldsm4(ah[mf][0], ah[mf][1], ah[mf][2], ah[mf][3], aB + off);
                ldsm4(alr[mf][0], alr[mf][1], alr[mf][2], alr[mf][3], alB + off);
            }
            #pragma unroll
            for (int nf16 = 0; nf16 < 2; nf16++) {
                unsigned off = (buf * 64 * ASTR + (wn + nf16 * 16 + nrow) * ASTR + ks + kcol) * 2;
                ldsm4(bh[nf16][0], bh[nf16][1], bh[nf16][2], bh[nf16][3], bB + off);
                ldsm4(blr[nf16][0], blr[nf16][1], blr[nf16][2], blr[nf16][3], blB + off);
            }
            #pragma unroll
            for (int mf = 0; mf < 2; mf++)
                #pragma unroll
                for (int nf = 0; nf < 4; nf++)
                    mma16816(c[mf][nf], ah[mf], &bh[nf >> 1][(nf & 1) * 2]);
            #pragma unroll
            for (int mf = 0; mf < 2; mf++)
                #pragma unroll
                for (int nf = 0; nf < 4; nf++)
                    mma16816(c[mf][nf], ah[mf], &blr[nf >> 1][(nf & 1) * 2]);
            #pragma unroll
            for (int mf = 0; mf < 2; mf++)
                #pragma unroll
                for (int nf = 0; nf < 4; nf++)
                    mma16816(c[mf][nf], alr[mf], &bh[nf >> 1][(nf & 1) * 2]);
        }
        __syncthreads();
    }

    int r = lane >> 2, cq = (lane & 3) * 2;
    #pragma unroll
    for (int mf = 0; mf < 2; mf++)
        #pragma unroll
        for (int nf = 0; nf < 4; nf++) {
            int row = m0 + wm + mf * 16 + r;
            int col = n0 + wn + nf * 8 + cq;
            float2 bv = *reinterpret_cast<const float2*>(biasP + col);
            __half* p = nullptr;
            size_t dstr = 0;
            if (col < c1)      { p = out1 + (size_t)row * s1 + col; dstr = s1; }
            else if (col < c2) { p = out2 + (size_t)row * s2 + (col - c1); dstr = s2; }
            if (!p) continue;
            if (row < M) {
                __half2 o = __floats2half2_rn(c[mf][nf][0] + bv.x, c[mf][nf][1] + bv.y);
                *reinterpret_cast<__half2*>(p) = o;
            }
            if (row + 8 < M) {
                __half2 o = __floats2half2_rn(c[mf][nf][2] + bv.x, c[mf][nf][3] + bv.y);
                *reinterpret_cast<__half2*>(p + 8 * dstr) = o;
            }
        }
}
#define GEMM_SMEM ((2 * 2 * 128 * ASTR + 2 * 2 * 64 * ASTR) * 2)

// ---------------- GraphNorm: fused stats + finalize (fp16 input) ----------------
#define PARTS 32
__global__ void gn_fused(const __half* __restrict__ x, const float* __restrict__ gn_ms,
                         int layer) {
    int g = blockIdx.x;
    int part = blockIdx.y;
    int f = threadIdx.x;
    __shared__ int lastFlag;
    if (f < HC) {
        int s0 = g_start[g], s1 = g_start[g + 1];
        float sum = 0.f, sq = 0.f;
        for (int n = s0 + part; n < s1; n += PARTS) {
            float v = __half2float(x[(size_t)n * HC + f]);
            sum += v;
            sq += v * v;
        }
        atomicAdd(&g_sum[g * HC + f], sum);
        atomicAdd(&g_sq[g * HC + f], sq);
    }
    __threadfence();
    __syncthreads();
    if (threadIdx.x == 0) {
        int t = atomicAdd(&g_gncnt[g], 1);
        lastFlag = (t == PARTS - 1);
    }
    __syncthreads();
    if (lastFlag && f < HC) {
        int idx = g * HC + f;
        float cnt = fmaxf((float)(g_start[g + 1] - g_start[g]), 1.f);
        float m = g_sum[idx] / cnt;
        float ms = gn_ms[layer * HC + f];
        float var = g_sq[idx] / cnt + m * m * (ms * ms - 2.f * ms);
        g_mean[idx] = m;
        g_rstd[idx] = 1.f / sqrtf(var + 1e-5f);
        g_sum[idx] = 0.f;
        g_sq[idx] = 0.f;
        if (f == 0) g_gncnt[g] = 0;
    }
}
// normalize + relu + split, fp16 input, 4-wide
__global__ void gn_norm_split(const __half* __restrict__ x,
                              const float* __restrict__ gn_w, const float* __restrict__ gn_b,
                              const float* __restrict__ gn_ms, int layer,
                              const int* __restrict__ batch) {
    int idx = blockIdx.x * blockDim.x + threadIdx.x;
    if (idx >= NN * HC / 4) return;
    int n = idx / (HC / 4), f4 = idx - n * (HC / 4);
    int f = f4 * 4;
    int g = batch[n];
    const __half2* xp = reinterpret_cast<const __half2*>(x);
    float2 x01 = __half22float2(xp[2 * idx]);
    float2 x23 = __half22float2(xp[2 * idx + 1]);
    float4 wv = *reinterpret_cast<const float4*>(gn_w + layer * HC + f);
    float4 bv = *reinterpret_cast<const float4*>(gn_b + layer * HC + f);
    float4 msv = *reinterpret_cast<const float4*>(gn_ms + layer * HC + f);
    float4 mv = *reinterpret_cast<const float4*>(g_mean + g * HC + f);
    float4 rv = *reinterpret_cast<const float4*>(g_rstd + g * HC + f);
    float o0 = fmaxf((x01.x - msv.x * mv.x) * rv.x * wv.x + bv.x, 0.f);
    float o1 = fmaxf((x01.y - msv.y * mv.y) * rv.y * wv.y + bv.y, 0.f);
    float o2 = fmaxf((x23.x - msv.z * mv.z) * rv.z * wv.z + bv.z, 0.f);
    float o3 = fmaxf((x23.y - msv.w * mv.w) * rv.w * wv.w + bv.w, 0.f);
    float h0 = __bfloat162float(__float2bfloat16(o0));
    float h1 = __bfloat162float(__float2bfloat16(o1));
    float h2 = __bfloat162float(__float2bfloat16(o2));
    float h3 = __bfloat162float(__float2bfloat16(o3));
    reinterpret_cast<uint2*>(g_ah)[idx] = make_uint2(pack2bf(o0, o1), pack2bf(o2, o3));
    reinterpret_cast<uint2*>(g_al)[idx] =
        make_uint2(pack2bf(o0 - h0, o1 - h1), pack2bf(o2 - h2, o3 - h3));
}

// ---------------- fused GATv2 attention (fp16 gathers + fp16 output) ----------------
__device__ __forceinline__ void h8_to_f(const uint4& u, float* dst) {
    const __half2* hp = reinterpret_cast<const __half2*>(&u);
    #pragma unroll
    for (int j = 0; j < 4; j++) {
        float2 f = __half22float2(hp[j]);
        dst[2 * j] = f.x;
        dst[2 * j + 1] = f.y;
    }
}
__global__ __launch_bounds__(256) void attn_fused(
    const float* __restrict__ att,
    __half* __restrict__ outbuf, int ostride, int addResid) {
    int idx = blockIdx.x * blockDim.x + threadIdx.x;
    if (idx >= NN * H) return;
    int n = idx / H;
    int h = idx - n * H;

    const uint4* xrp = reinterpret_cast<const uint4*>(g_xlr + (size_t)n * 352 + 176 + h * HIDF);
    const float* atp = att + h * HIDF;
    float xr[16], at[16];
    {
        uint4 u0 = xrp[0], u1 = xrp[1];
        h8_to_f(u0, xr);
        h8_to_f(u1, xr + 8);
    }
    #pragma unroll
    for (int i = 0; i < 4; i++) {
        float4 a = reinterpret_cast<const float4*>(atp)[i];
        at[i*4+0] = a.x; at[i*4+1] = a.y; at[i*4+2] = a.z; at[i*4+3] = a.w;
    }

    float den = 0.f;
    float acc[16];
    #pragma unroll
    for (int j = 0; j < 16; j++) acc[j] = 0.f;

    int e = g_rowptr[n], e1 = g_rowptr[n + 1];

    for (; e + 2 <= e1; e += 2) {
        int s0 = g_csr[e];
        int s1 = g_csr[e + 1];
        const uint4* p0 = reinterpret_cast<const uint4*>(g_xlr + (size_t)s0 * 352 + h * HIDF);
        const uint4* p1 = reinterpret_cast<const uint4*>(g_xlr + (size_t)s1 * 352 + h * HIDF);
        uint4 u00 = p0[0], u01 = p0[1], u10 = p1[0], u11 = p1[1];
        float xl0[16], xl1[16];
        h8_to_f(u00, xl0); h8_to_f(u01, xl0 + 8);
        h8_to_f(u10, xl1); h8_to_f(u11, xl1 + 8);
        float a0 = 0.f, a1 = 0.f;
        #pragma unroll
        for (int j = 0; j < 16; j++) {
            float t0 = xl0[j] + xr[j];
            t0 = t0 > 0.f ? t0 : 0.2f * t0;
            a0 = fmaf(t0, at[j], a0);
            float t1 = xl1[j] + xr[j];
            t1 = t1 > 0.f ? t1 : 0.2f * t1;
            a1 = fmaf(t1, at[j], a1);
        }
        float ex0 = __expf(a0);
        float ex1 = __expf(a1);
        den += ex0 + ex1;
        #pragma unroll
        for (int j = 0; j < 16; j++)
            acc[j] = fmaf(ex1, xl1[j], fmaf(ex0, xl0[j], acc[j]));
    }
    if (e < e1) {
        int s = g_csr[e];
        const uint4* pl = reinterpret_cast<const uint4*>(g_xlr + (size_t)s * 352 + h * HIDF);
        uint4 u0 = pl[0], u1 = pl[1];
        float xl[16];
        h8_to_f(u0, xl);
        h8_to_f(u1, xl + 8);
        float alpha = 0.f;
        #pragma unroll
        for (int j = 0; j < 16; j++) {
            float v = xl[j] + xr[j];
            v = v > 0.f ? v : 0.2f * v;
            alpha = fmaf(v, at[j], alpha);
        }
        float ex = __expf(alpha);
        den += ex;
        #pragma unroll
        for (int j = 0; j < 16; j++) acc[j] = fmaf(ex, xl[j], acc[j]);
    }
    float inv = 1.f / (den + 1e-16f);
    __half2* op = reinterpret_cast<__half2*>(outbuf + (size_t)n * ostride + h * HIDF);
    #pragma unroll
    for (int j = 0; j < 8; j++) {
        float b0 = 0.f, b1 = 0.f;
        if (addResid) {
            float2 b = __half22float2(op[j]);
            b0 = b.x; b1 = b.y;
        }
        op[j] = __floats2half2_rn(b0 + acc[2 * j] * inv, b1 + acc[2 * j + 1] * inv);
    }
}

// ---------------- conv5 head mean + relu ----------------
__global__ void head_mean_relu() {
    int idx = blockIdx.x * blockDim.x + threadIdx.x;
    if (idx >= NN * HIDF) return;
    int n = idx / HIDF, c = idx - n * HIDF;
    float res = __half2float(g_res16[idx]);
    float s = 0.f;
    #pragma unroll
    for (int h = 0; h < H; h++) s += __half2float(g_buf[(size_t)n * HC + h * HIDF + c]);
    g_out16[idx] = fmaxf(res + s * (1.f / (float)H), 0.f);
}

// ---------------- final fused MLP ----------------
__global__ void mlp(const float* __restrict__ Wo1, const float* __restrict__ bo1,
                    const float* __restrict__ Wo2, const float* __restrict__ bo2,
                    const float* __restrict__ Wc,  const float* __restrict__ bc,
                    float* __restrict__ out) {
    __shared__ float w1[16 * 16], w2[16 * 32], w3[32 * 10], b1[16], b2[32], b3[10];
    int tid = threadIdx.x;
    if (tid < 256) w1[tid] = Wo1[tid];
    for (int t = tid; t < 512; t += blockDim.x) w2[t] = Wo2[t];
    for (int t = tid; t < 320; t += blockDim.x) w3[t] = Wc[t];
    if (tid < 16) b1[tid] = bo1[tid];
    if (tid < 32) b2[tid] = bo2[tid];
    if (tid < 10) b3[tid] = bc[tid];
    __syncthreads();
    int n = blockIdx.x * blockDim.x + tid;
    if (n >= NN) return;
    float a[16];
    #pragma unroll
    for (int i = 0; i < 16; i++) a[i] = g_out16[(size_t)n * 16 + i];
    float t1[16];
    #pragma unroll
    for (int j = 0; j < 16; j++) {
        float acc = b1[j];
        #pragma unroll
        for (int i = 0; i < 16; i++) acc += a[i] * w1[i * 16 + j];
        t1[j] = fmaxf(acc, 0.f);
    }
    float t2[32];
    #pragma unroll
    for (int j = 0; j < 32; j++) {
        float acc = b2[j];
        #pragma unroll
        for (int i = 0; i < 16; i++) acc += t1[i] * w2[i * 32 + j];
        t2[j] = fmaxf(acc, 0.f);
    }
    #pragma unroll
    for (int j = 0; j < 10; j++) {
        float acc = b3[j];
        #pragma unroll
        for (int k = 0; k < 32; k++) acc += t2[k] * w3[k * 10 + j];
        out[(size_t)n * 10 + j] = acc;
    }
}

// ---------------- host launch ----------------
extern "C" void kernel_launch(void* const* d_in, const int* in_sizes, int n_in,
                              void* d_out, int out_size) {
    const float* x        = (const float*)d_in[0];
    const int*   ei       = (const int*)d_in[1];
    const int*   batch    = (const int*)d_in[2];
    const float* W_pre    = (const float*)d_in[3];
    const float* b_pre    = (const float*)d_in[4];
    const float* gn_w     = (const float*)d_in[5];
    const float* gn_b     = (const float*)d_in[6];
    const float* gn_ms    = (const float*)d_in[7];
    const float* conv_Wl  = (const float*)d_in[8];
    const float* conv_Wr  = (const float*)d_in[9];
    const float* conv_att = (const float*)d_in[10];
    const float* conv_b   = (const float*)d_in[11];
    const float* conv_Wres= (const float*)d_in[12];
    const float* c5_Wl    = (const float*)d_in[13];
    const float* c5_Wr    = (const float*)d_in[14];
    const float* c5_att   = (const float*)d_in[15];
    const float* c5_b     = (const float*)d_in[16];
    const float* c5_Wres  = (const float*)d_in[17];
    const float* W_o1     = (const float*)d_in[18];
    const float* b_o1     = (const float*)d_in[19];
    const float* W_o2     = (const float*)d_in[20];
    const float* b_o2     = (const float*)d_in[21];
    const float* W_cls    = (const float*)d_in[22];
    const float* b_cls    = (const float*)d_in[23];
    float* out = (float*)d_out;

    float *p_sum, *p_sq, *p_pbias;
    __half *p_xlr, *p_res, *p_buf, *p_res16;
    __nv_bfloat16 *p_ah, *p_al, *p_xh, *p_xlo, *p_pwh, *p_pwl;
    int *p_start, *p_deg, *p_rowptr, *p_bsum, *p_boff, *p_gncnt;
    cudaGetSymbolAddress((void**)&p_xlr, g_xlr);
    cudaGetSymbolAddress((void**)&p_res, g_res);
    cudaGetSymbolAddress((void**)&p_buf, g_buf);
    cudaGetSymbolAddress((void**)&p_res16, g_res16);
    cudaGetSymbolAddress((void**)&p_sum, g_sum);
    cudaGetSymbolAddress((void**)&p_sq, g_sq);
    cudaGetSymbolAddress((void**)&p_pbias, g_pbias);
    cudaGetSymbolAddress((void**)&p_ah, g_ah);
    cudaGetSymbolAddress((void**)&p_al, g_al);
    cudaGetSymbolAddress((void**)&p_xh, g_xh);
    cudaGetSymbolAddress((void**)&p_xlo, g_xlo);
    cudaGetSymbolAddress((void**)&p_pwh, g_pwh);
    cudaGetSymbolAddress((void**)&p_pwl, g_pwl);
    cudaGetSymbolAddress((void**)&p_start, g_start);
    cudaGetSymbolAddress((void**)&p_deg, g_deg);
    cudaGetSymbolAddress((void**)&p_rowptr, g_rowptr);
    cudaGetSymbolAddress((void**)&p_bsum, g_bsum);
    cudaGetSymbolAddress((void**)&p_boff, g_boff);
    cudaGetSymbolAddress((void**)&p_gncnt, g_gncnt);

    static int initDone = 0;
    static cudaStream_t sSide;
    static cudaEvent_t evFork, evJoin;
    if (!initDone) {
        cudaFuncSetAttribute(gemm3x, cudaFuncAttributeMaxDynamicSharedMemorySize, GEMM_SMEM);
        cudaStreamCreateWithFlags(&sSide, cudaStreamNonBlocking);
        cudaEventCreateWithFlags(&evFork, cudaEventDisableTiming);
        cudaEventCreateWithFlags(&evJoin, cudaEventDisableTiming);
        initDone = 1;
    }

    auto gemm = [&](const __nv_bfloat16* Ah, const __nv_bfloat16* Al, int woff, int bslot,
                    __half* o1, int s1v, int c1v, __half* o2, int s2v, int c2v,
                    int NPv, int KPv) {
        dim3 grid(NPv / 64, (NN + 127) / 128);
        gemm3x<<<grid, 256, GEMM_SMEM>>>(Ah, Al, p_pwh + woff, p_pwl + woff,
                                         p_pbias + bslot * NP_CONV,
                                         o1, s1v, c1v, o2, s2v, c2v, NN, KPv);
    };
    auto graphnorm = [&](int layer) {
        dim3 sgrid(G, PARTS);
        gn_fused<<<sgrid, 192>>>(p_res, gn_ms, layer);
        gn_norm_split<<<(NN * HC / 4 + 255) / 256, 256>>>(p_res, gn_w, gn_b, gn_ms, layer, batch);
    };

    // fork side stream: CSR build
    cudaEventRecord(evFork, 0);
    cudaStreamWaitEvent(sSide, evFork, 0);
    {
        const int NBLK = (NN + SCAN_B - 1) / SCAN_B;
        cudaMemsetAsync(p_deg, 0, NN * sizeof(int), sSide);
        deg_count<<<(EP + 255) / 256, 256, 0, sSide>>>(ei);
        scan1<<<NBLK, SCAN_B, 0, sSide>>>(p_deg, p_rowptr, p_bsum, NN);
        scan1<<<1, SCAN_B, 0, sSide>>>(p_bsum, p_boff, nullptr, NBLK);
        scan_add<<<NBLK, SCAN_B, 0, sSide>>>(p_rowptr, p_boff, NN);
        csr_scatter<<<(EP + 255) / 256, 256, 0, sSide>>>(ei);
        cudaEventRecord(evJoin, sSide);
    }

    // main stream
    cudaMemsetAsync(p_start, 0xFF, (G + 1) * sizeof(int));
    cudaMemsetAsync(p_sum, 0, G * HC * sizeof(float));
    cudaMemsetAsync(p_sq, 0, G * HC * sizeof(float));
    cudaMemsetAsync(p_gncnt, 0, G * sizeof(int));

    pack_all<<<(PACK_TOTAL + 255) / 256, 256>>>(W_pre, conv_Wl, conv_Wr, conv_Wres,
                                                c5_Wl, c5_Wr, c5_Wres,
                                                b_pre, conv_b, c5_b);
    asplit_pre<<<(NN * KPRE / 4 + 255) / 256, 256>>>(x);
    seg_mark<<<(NN + 255) / 256, 256>>>(batch, p_start);
    // pre-layer: all output cols fp16 -> out2 = g_res (c1 = 0)
    gemm(p_xh, p_xlo, OFFP_PRE, 0, nullptr, 0, 0, p_res, HC, HC, NP_PRE, KPRE);
    seg_fix<<<1, 32>>>(p_start);
    graphnorm(0);

    cudaStreamWaitEvent(0, evJoin, 0);

    const int attGrid = (NN * H + 255) / 256;

    for (int L = 0; L < 4; L++) {
        gemm(p_ah, p_al, OFFP_CONV + L * SZP_CONV, 1 + L,
             p_xlr, 352, 352, p_res, HC, 528, NP_CONV, KP);
        attn_fused<<<attGrid, 256>>>(conv_att + L * H * HIDF, p_res, HC, 1);
        graphnorm(L + 1);
    }

    gemm(p_ah, p_al, OFFP_C5, 5,
         p_xlr, 352, 352, p_res16, HIDF, 368, NP_C5, KP);
    attn_fused<<<attGrid, 256>>>(c5_att, p_buf, HC, 0);
    head_mean_relu<<<(NN * HIDF + 255) / 256, 256>>>();

    mlp<<<(NN + 255) / 256, 256>>>(W_o1, b_o1, W_o2, b_o2, W_cls, b_cls, out);
}